// round 3
// baseline (speedup 1.0000x reference)
#include <cuda_runtime.h>
#include <cstdint>

#define Hc 128
#define Nc 128
#define Lc 2048

typedef unsigned long long ull;

// Scratch for synthesized kernel Kl[h,l]  (1 MB)
__device__ float g_Kl[Hc * Lc];

// ---------------------------------------------------------------------------
// packed fp32x2 FMA: acc (2 lanes) += a * b
// ---------------------------------------------------------------------------
__device__ __forceinline__ void ffma2(ull& acc, ull a, ull b) {
    asm("fma.rn.f32x2 %0, %1, %2, %0;" : "+l"(acc) : "l"(a), "l"(b));
}
__device__ __forceinline__ ull pack2(float lo, float hi) {
    ull r;
    asm("mov.b64 %0, {%1, %2};" : "=l"(r) : "f"(lo), "f"(hi));
    return r;
}
__device__ __forceinline__ float lo32(ull v) { float a,b; asm("mov.b64 {%0,%1}, %2;" : "=f"(a), "=f"(b) : "l"(v)); return a; }
__device__ __forceinline__ float hi32(ull v) { float a,b; asm("mov.b64 {%0,%1}, %2;" : "=f"(a), "=f"(b) : "l"(v)); return b; }

// ---------------------------------------------------------------------------
// Kernel 1: Kl[h,l] = sum_n C[h,n] * K[l,h,n]
// Each warp handles 8 consecutive l rows: 8 independent LDG.128 up front
// (MLP=8), then 8 shfl reductions. Warp reads 512B contiguous per row.
// ---------------------------------------------------------------------------
__global__ __launch_bounds__(256) void kl_synth_kernel(
    const float* __restrict__ K,   // (L,H,N)
    const float* __restrict__ C)   // (H,N)
{
    const int h    = blockIdx.y;
    const int warp = threadIdx.x >> 5;
    const int lane = threadIdx.x & 31;
    const int l0   = blockIdx.x * 64 + warp * 8;

    const float4 c4 = reinterpret_cast<const float4*>(C + h * Nc)[lane];

    float4 k4[8];
    #pragma unroll
    for (int r = 0; r < 8; ++r) {
        const size_t base = ((size_t)(l0 + r) * Hc + h) * Nc;
        k4[r] = reinterpret_cast<const float4*>(K + base)[lane];
    }

    float s[8];
    #pragma unroll
    for (int r = 0; r < 8; ++r)
        s[r] = c4.x * k4[r].x + c4.y * k4[r].y + c4.z * k4[r].z + c4.w * k4[r].w;

    #pragma unroll
    for (int r = 0; r < 8; ++r) {
        #pragma unroll
        for (int o = 16; o > 0; o >>= 1)
            s[r] += __shfl_xor_sync(0xFFFFFFFFu, s[r], o);
    }
    if (lane == 0) {
        #pragma unroll
        for (int r = 0; r < 8; ++r)
            g_Kl[h * Lc + l0 + r] = s[r];
    }
}

// ---------------------------------------------------------------------------
// Kernel 2: depthwise 'same' conv + skip, packed f32x2 math.
//
//   y[t] = sum_{m=0}^{2047} k[m] * u[t + 1023 - m]   (u zero-padded)
//
// m paired with SWAPPED k pairs so the u operand pair is consecutive:
//   even t:  pair (m=2p+1, m=2p):
//      k[2p+1]*u[x] + k[2p]*u[x+1],  x = t+1022-2p  (even)  -> aligned float2
//      k2e[p] = {k[2p+1], k[2p]},  p = 0..1023 covers m = 0..2047 fully.
//   odd t:   pair (m=2p, m=2p-1):
//      k[2p]*u[x] + k[2p-1]*u[x+1],  x = t+1023-2p  (even)
//      k2o[p] = {k[2p], k[2p-1]}, k2o[0] = {k[0], 0};  p = 0..1023 covers
//      m = 0..2046; fixup term m=2047: y[t] += k[2047]*u[t-1024].
//
// Thread layout: tid = P*128 + i  (P = parity). Thread owns 8 outputs
//   t = 16*i + 2*j + P,  j = 0..7  (stride-2, single parity -> all aligned).
//
// Padded u: a = uidx + 1024, a in [0,4096). float2 index F = a/2 in [0,2048).
// Operand for (j, p):  F = 8i + j + 1023 + P - p.
// Chunk of 16 p:  window F in [F0, F0+23], F0 = 8i + 1008 - p0 (even).
// u stored as float4 blocks Q = F/2, skewed: loc(Q) = Q + (Q>>2)
//   -> LDS.128 at lane-stride 4 float4s is bank-conflict-free.
//   Q0 = 4i + 504 - 8c  (mult of 4), so within-chunk offsets b + (b>>2)
//   are compile-time constants.
// ---------------------------------------------------------------------------
__global__ __launch_bounds__(256) void conv_kernel(
    const float* __restrict__ u,   // (H,L)
    const float* __restrict__ D,   // (H,)
    float* __restrict__ y)         // (H,L)
{
    __shared__ ulonglong2 suq[1280];   // skewed float4 u blocks (20.0 KB)
    __shared__ ull k2e[1024];          // 8 KB
    __shared__ ull k2o[1024];          // 8 KB
    __shared__ float ybuf[Lc];         // 8 KB  -> total ~44.5 KB

    const int h   = blockIdx.x;
    const int tid = threadIdx.x;

    // ---- build swapped k-pair tables ----
    const float* kl = g_Kl + h * Lc;
    for (int p = tid; p < 1024; p += 256) {
        float ke = kl[2 * p];          // k[2p]
        float ko = kl[2 * p + 1];      // k[2p+1]
        k2e[p] = pack2(ko, ke);                        // {k[2p+1], k[2p]}
        k2o[p] = pack2(ke, p ? kl[2 * p - 1] : 0.0f);  // {k[2p],  k[2p-1]}
    }

    // ---- fill skewed padded u (valid a in [1024, 3072)) ----
    const float4* ug4 = reinterpret_cast<const float4*>(u + h * Lc);
    for (int Q = tid; Q < 1024; Q += 256) {
        float4 v = make_float4(0.f, 0.f, 0.f, 0.f);
        if (Q >= 256 && Q < 768) v = ug4[Q - 256];
        ulonglong2 w;
        w.x = pack2(v.x, v.y);
        w.y = pack2(v.z, v.w);
        suq[Q + (Q >> 2)] = w;
    }
    __syncthreads();

    const int i = tid & 127;
    const int P = tid >> 7;            // 0 = even outputs, 1 = odd outputs
    const ull* ktab = P ? k2o : k2e;

    ull acc[8];
    #pragma unroll
    for (int j = 0; j < 8; ++j) acc[j] = 0ULL;

    int Q0 = 4 * i + 504;              // decreases by 8 each chunk

    for (int c = 0; c < 64; ++c) {
        // load 24-float2 window (12 conflict-free LDS.128)
        ull W[24];
        const int base = Q0 + (Q0 >> 2);   // Q0 multiple of 4 -> exact
        #pragma unroll
        for (int b = 0; b < 12; ++b) {
            ulonglong2 v = suq[base + b + (b >> 2)];
            W[2 * b]     = v.x;
            W[2 * b + 1] = v.y;
        }
        // load 16 swapped k-pairs (broadcast)
        ull kk[16];
        #pragma unroll
        for (int d = 0; d < 16; ++d) kk[d] = ktab[16 * c + d];

        #pragma unroll
        for (int dp = 0; dp < 16; ++dp) {
            #pragma unroll
            for (int j = 0; j < 8; ++j)
                ffma2(acc[j], kk[dp], W[15 - dp + j + P]);
        }
        Q0 -= 8;
    }

    // ---- epilogue ----
    const float dh = D[h];
    const float* suf = reinterpret_cast<const float*>(suq);
    float k2047 = lo32(k2e[1023]);     // k[2047]

    #pragma unroll
    for (int j = 0; j < 8; ++j) {
        const int t = 16 * i + 2 * j + P;
        float out = lo32(acc[j]) + hi32(acc[j]);
        if (P) {
            // fixup m = 2047: u index t-1024 -> a = t
            int a = t;
            int Q = a >> 2;
            out += k2047 * suf[(Q + (Q >> 2)) * 4 + (a & 3)];
        }
        // skip connection: u[t] -> a = t + 1024
        int a = t + 1024;
        int Q = a >> 2;
        out += dh * suf[(Q + (Q >> 2)) * 4 + (a & 3)];
        ybuf[t] = out;
    }
    __syncthreads();

    // coalesced store
    const float4* yb4 = reinterpret_cast<const float4*>(ybuf);
    float4* yg4 = reinterpret_cast<float4*>(y + h * Lc);
    for (int q = tid; q < Lc / 4; q += 256) yg4[q] = yb4[q];
}

// ---------------------------------------------------------------------------
extern "C" void kernel_launch(void* const* d_in, const int* in_sizes, int n_in,
                              void* d_out, int out_size)
{
    const float* u = nullptr;
    const float* C = nullptr;
    const float* D = nullptr;
    const float* K = nullptr;
    for (int i = 0; i < n_in; ++i) {
        switch (in_sizes[i]) {
            case Hc * Lc:  u = (const float*)d_in[i]; break;
            case Hc * Nc:  C = (const float*)d_in[i]; break;
            case Hc:       D = (const float*)d_in[i]; break;
            default:
                if (in_sizes[i] == Lc * Hc * Nc) K = (const float*)d_in[i];
                break;
        }
    }

    float* y = (float*)d_out;

    dim3 grid1(Lc / 64, Hc);           // 32 x 128 blocks, 8 l per warp
    kl_synth_kernel<<<grid1, 256>>>(K, C);
    conv_kernel<<<Hc, 256>>>(u, D, y);
}

// round 4
// speedup vs baseline: 1.8064x; 1.8064x over previous
#include <cuda_runtime.h>
#include <cstdint>

#define Hc 128
#define Nc 128
#define Lc 2048

typedef unsigned long long ull;

// Scratch for synthesized kernel Kl[h,l]  (1 MB)
__device__ float g_Kl[Hc * Lc];

// ---------------------------------------------------------------------------
// packed fp32x2 FMA: acc (2 lanes) += a * b
// ---------------------------------------------------------------------------
__device__ __forceinline__ void ffma2(ull& acc, ull a, ull b) {
    asm("fma.rn.f32x2 %0, %1, %2, %0;" : "+l"(acc) : "l"(a), "l"(b));
}
__device__ __forceinline__ ull pack2(float lo, float hi) {
    ull r;
    asm("mov.b64 %0, {%1, %2};" : "=l"(r) : "f"(lo), "f"(hi));
    return r;
}
__device__ __forceinline__ float lo32(ull v) { float a,b; asm("mov.b64 {%0,%1}, %2;" : "=f"(a), "=f"(b) : "l"(v)); return a; }
__device__ __forceinline__ float hi32(ull v) { float a,b; asm("mov.b64 {%0,%1}, %2;" : "=f"(a), "=f"(b) : "l"(v)); return b; }

// ---------------------------------------------------------------------------
// Kernel 1: Kl[h,l] = sum_n C[h,n] * K[l,h,n]
// Each warp handles 8 consecutive l rows (MLP=8), shfl reduction.
// ---------------------------------------------------------------------------
__global__ __launch_bounds__(256) void kl_synth_kernel(
    const float* __restrict__ K,   // (L,H,N)
    const float* __restrict__ C)   // (H,N)
{
    const int h    = blockIdx.y;
    const int warp = threadIdx.x >> 5;
    const int lane = threadIdx.x & 31;
    const int l0   = blockIdx.x * 64 + warp * 8;

    const float4 c4 = reinterpret_cast<const float4*>(C + h * Nc)[lane];

    float4 k4[8];
    #pragma unroll
    for (int r = 0; r < 8; ++r) {
        const size_t base = ((size_t)(l0 + r) * Hc + h) * Nc;
        k4[r] = reinterpret_cast<const float4*>(K + base)[lane];
    }

    float s[8];
    #pragma unroll
    for (int r = 0; r < 8; ++r)
        s[r] = c4.x * k4[r].x + c4.y * k4[r].y + c4.z * k4[r].z + c4.w * k4[r].w;

    #pragma unroll
    for (int r = 0; r < 8; ++r) {
        #pragma unroll
        for (int o = 16; o > 0; o >>= 1)
            s[r] += __shfl_xor_sync(0xFFFFFFFFu, s[r], o);
    }
    if (lane == 0) {
        #pragma unroll
        for (int r = 0; r < 8; ++r)
            g_Kl[h * Lc + l0 + r] = s[r];
    }
}

// ---------------------------------------------------------------------------
// Kernel 2: depthwise 'same' conv + skip, packed f32x2 math.
// (Math identical to R3 — which verified at rel_err 3.3e-7 — but the inner
// loop is duplicated per parity P so ALL W indices are compile-time and the
// 24-entry window stays in registers. P is uniform per warp: no divergence.)
// ---------------------------------------------------------------------------
__global__ __launch_bounds__(256) void conv_kernel(
    const float* __restrict__ u,   // (H,L)
    const float* __restrict__ D,   // (H,)
    float* __restrict__ y)         // (H,L)
{
    __shared__ ulonglong2 suq[1280];   // skewed float4 u blocks (20.0 KB)
    __shared__ ull k2e[1024];          // 8 KB
    __shared__ ull k2o[1024];          // 8 KB
    __shared__ float ybuf[Lc];         // 8 KB

    const int h   = blockIdx.x;
    const int tid = threadIdx.x;

    // ---- build swapped k-pair tables ----
    const float* kl = g_Kl + h * Lc;
    for (int p = tid; p < 1024; p += 256) {
        float ke = kl[2 * p];          // k[2p]
        float ko = kl[2 * p + 1];      // k[2p+1]
        k2e[p] = pack2(ko, ke);                        // {k[2p+1], k[2p]}
        k2o[p] = pack2(ke, p ? kl[2 * p - 1] : 0.0f);  // {k[2p],  k[2p-1]}
    }

    // ---- fill skewed padded u (valid a in [1024, 3072)) ----
    const float4* ug4 = reinterpret_cast<const float4*>(u + h * Lc);
    for (int Q = tid; Q < 1024; Q += 256) {
        float4 v = make_float4(0.f, 0.f, 0.f, 0.f);
        if (Q >= 256 && Q < 768) v = ug4[Q - 256];
        ulonglong2 w;
        w.x = pack2(v.x, v.y);
        w.y = pack2(v.z, v.w);
        suq[Q + (Q >> 2)] = w;
    }
    __syncthreads();

    const int i = tid & 127;
    const int P = tid >> 7;            // 0 = even outputs, 1 = odd outputs

    ull acc[8];
    #pragma unroll
    for (int j = 0; j < 8; ++j) acc[j] = 0ULL;

    int Q0 = 4 * i + 504;              // decreases by 8 each chunk

    if (P == 0) {
        #pragma unroll 1
        for (int c = 0; c < 64; ++c) {
            ull W[24];
            const int base = Q0 + (Q0 >> 2);   // Q0 multiple of 4 -> exact
            #pragma unroll
            for (int b = 0; b < 12; ++b) {
                ulonglong2 v = suq[base + b + (b >> 2)];
                W[2 * b]     = v.x;
                W[2 * b + 1] = v.y;
            }
            #pragma unroll
            for (int dp = 0; dp < 16; ++dp) {
                const ull kv = k2e[16 * c + dp];
                #pragma unroll
                for (int j = 0; j < 8; ++j)
                    ffma2(acc[j], kv, W[15 - dp + j]);
            }
            Q0 -= 8;
        }
    } else {
        #pragma unroll 1
        for (int c = 0; c < 64; ++c) {
            ull W[24];
            const int base = Q0 + (Q0 >> 2);
            #pragma unroll
            for (int b = 0; b < 12; ++b) {
                ulonglong2 v = suq[base + b + (b >> 2)];
                W[2 * b]     = v.x;
                W[2 * b + 1] = v.y;
            }
            #pragma unroll
            for (int dp = 0; dp < 16; ++dp) {
                const ull kv = k2o[16 * c + dp];
                #pragma unroll
                for (int j = 0; j < 8; ++j)
                    ffma2(acc[j], kv, W[16 - dp + j]);
            }
            Q0 -= 8;
        }
    }

    // ---- epilogue ----
    const float dh = D[h];
    const float* suf = reinterpret_cast<const float*>(suq);
    float k2047 = lo32(k2e[1023]);     // k[2047]

    #pragma unroll
    for (int j = 0; j < 8; ++j) {
        const int t = 16 * i + 2 * j + P;
        float out = lo32(acc[j]) + hi32(acc[j]);
        if (P) {
            // fixup m = 2047: u index t-1024 -> a = t
            int a = t;
            int Q = a >> 2;
            out += k2047 * suf[(Q + (Q >> 2)) * 4 + (a & 3)];
        }
        // skip connection: u[t] -> a = t + 1024
        int a = t + 1024;
        int Q = a >> 2;
        out += dh * suf[(Q + (Q >> 2)) * 4 + (a & 3)];
        ybuf[t] = out;
    }
    __syncthreads();

    // coalesced store
    const float4* yb4 = reinterpret_cast<const float4*>(ybuf);
    float4* yg4 = reinterpret_cast<float4*>(y + h * Lc);
    for (int q = tid; q < Lc / 4; q += 256) yg4[q] = yb4[q];
}

// ---------------------------------------------------------------------------
extern "C" void kernel_launch(void* const* d_in, const int* in_sizes, int n_in,
                              void* d_out, int out_size)
{
    const float* u = nullptr;
    const float* C = nullptr;
    const float* D = nullptr;
    const float* K = nullptr;
    for (int i = 0; i < n_in; ++i) {
        switch (in_sizes[i]) {
            case Hc * Lc:  u = (const float*)d_in[i]; break;
            case Hc * Nc:  C = (const float*)d_in[i]; break;
            case Hc:       D = (const float*)d_in[i]; break;
            default:
                if (in_sizes[i] == Lc * Hc * Nc) K = (const float*)d_in[i];
                break;
        }
    }

    float* y = (float*)d_out;

    dim3 grid1(Lc / 64, Hc);           // 32 x 128 blocks, 8 l per warp
    kl_synth_kernel<<<grid1, 256>>>(K, C);
    conv_kernel<<<Hc, 256>>>(u, D, y);
}

// round 5
// speedup vs baseline: 1.8514x; 1.0249x over previous
#include <cuda_runtime.h>
#include <cstdint>

#define Hc 128
#define Nc 128
#define Lc 2048

typedef unsigned long long ull;

// Scratch for synthesized kernel Kl[h,l]  (1 MB)
__device__ float g_Kl[Hc * Lc];

// ---------------------------------------------------------------------------
__device__ __forceinline__ void ffma2(ull& acc, ull a, ull b) {
    asm("fma.rn.f32x2 %0, %1, %2, %0;" : "+l"(acc) : "l"(a), "l"(b));
}
__device__ __forceinline__ ull pack2(float lo, float hi) {
    ull r;
    asm("mov.b64 %0, {%1, %2};" : "=l"(r) : "f"(lo), "f"(hi));
    return r;
}
__device__ __forceinline__ float lo32(ull v) { float a,b; asm("mov.b64 {%0,%1}, %2;" : "=f"(a), "=f"(b) : "l"(v)); return a; }
__device__ __forceinline__ float hi32(ull v) { float a,b; asm("mov.b64 {%0,%1}, %2;" : "=f"(a), "=f"(b) : "l"(v)); return b; }

// ---------------------------------------------------------------------------
// Kernel 1: Kl[h,l] = sum_n C[h,n] * K[l,h,n]
// One block per l: K[l,:,:] is a contiguous 64KB slab. Each warp reads 16
// consecutive h-rows (8KB coalesced, MLP=16, streaming .cs). C is L1-resident
// across blocks on the same SM. shfl-reduce per row, lane0 scatter-stores.
// ---------------------------------------------------------------------------
__global__ __launch_bounds__(256) void kl_synth_kernel(
    const float* __restrict__ K,   // (L,H,N)
    const float* __restrict__ C)   // (H,N)
{
    const int l    = blockIdx.x;
    const int warp = threadIdx.x >> 5;
    const int lane = threadIdx.x & 31;
    const int h0   = warp * 16;

    const float4* Kl4 = reinterpret_cast<const float4*>(K + (size_t)l * (Hc * Nc));

    // 16 independent 512B row loads in flight
    float4 kv[16];
    #pragma unroll
    for (int r = 0; r < 16; ++r)
        kv[r] = __ldcs(Kl4 + (h0 + r) * (Nc / 4) + lane);

    float s[16];
    #pragma unroll
    for (int r = 0; r < 16; ++r) {
        const float4 c4 = reinterpret_cast<const float4*>(C + (h0 + r) * Nc)[lane];
        s[r] = c4.x * kv[r].x + c4.y * kv[r].y + c4.z * kv[r].z + c4.w * kv[r].w;
    }

    #pragma unroll
    for (int r = 0; r < 16; ++r) {
        #pragma unroll
        for (int o = 16; o > 0; o >>= 1)
            s[r] += __shfl_xor_sync(0xFFFFFFFFu, s[r], o);
    }

    if (lane == 0) {
        #pragma unroll
        for (int r = 0; r < 16; ++r)
            g_Kl[(h0 + r) * Lc + l] = s[r];
    }
}

// ---------------------------------------------------------------------------
// Kernel 2: depthwise 'same' conv + skip, packed f32x2.
//
// Identity (verified rel_err 3.3e-7 in R3/R4):
//   even t=16i+2j,  pair p: k[2p+1]*u2[F].lo + k[2p]*u2[F].hi, F = 8i+j+1023-p
//   odd  t=16i+2j+1,pair p: k[2p]*u2[F'].lo + k[2p-1]*u2[F'].hi, F' = F+1
// Same 24-float2 window serves BOTH parities -> thread computes 16 outputs
// (accE[8], accO[8]); m-range split across two thread-halves (32 chunks each),
// partials combined in smem. Per chunk: 12 LDS.128 + 32 bcast + 256 FFMA2.
// ---------------------------------------------------------------------------
__global__ __launch_bounds__(256) void conv_kernel(
    const float* __restrict__ u,   // (H,L)
    const float* __restrict__ D,   // (H,)
    float* __restrict__ y)         // (H,L)
{
    __shared__ ulonglong2 suq[1280];   // skewed float4 u blocks (20.0 KB)
    __shared__ ull k2e[1024];          // 8 KB
    __shared__ ull k2o[1024];          // 8 KB
    __shared__ float ybuf[Lc];         // 8 KB

    const int h   = blockIdx.x;
    const int tid = threadIdx.x;

    // ---- build swapped k-pair tables ----
    const float* kl = g_Kl + h * Lc;
    for (int p = tid; p < 1024; p += 256) {
        float ke = kl[2 * p];
        float ko = kl[2 * p + 1];
        k2e[p] = pack2(ko, ke);                        // {k[2p+1], k[2p]}
        k2o[p] = pack2(ke, p ? kl[2 * p - 1] : 0.0f);  // {k[2p],  k[2p-1]}
    }

    // ---- fill skewed padded u (valid a in [1024, 3072)) ----
    const float4* ug4 = reinterpret_cast<const float4*>(u + h * Lc);
    for (int Q = tid; Q < 1024; Q += 256) {
        float4 v = make_float4(0.f, 0.f, 0.f, 0.f);
        if (Q >= 256 && Q < 768) v = ug4[Q - 256];
        ulonglong2 w;
        w.x = pack2(v.x, v.y);
        w.y = pack2(v.z, v.w);
        suq[Q + (Q >> 2)] = w;
    }
    __syncthreads();

    const int i    = tid & 127;        // output tile: t in [16i, 16i+16)
    const int half = tid >> 7;         // m-half: chunks [32*half, 32*half+32)

    ull accE[8], accO[8];
    #pragma unroll
    for (int j = 0; j < 8; ++j) { accE[j] = 0ULL; accO[j] = 0ULL; }

    int Q0 = 4 * i + 504 - 256 * half; // = 4i + 504 - 8c at c = 32*half
    const int pbase = 512 * half;      // p0 of first chunk

    #pragma unroll 1
    for (int cc = 0; cc < 32; ++cc) {
        ull W[24];
        const int base = Q0 + (Q0 >> 2);   // Q0 multiple of 4 -> exact skew
        #pragma unroll
        for (int b = 0; b < 12; ++b) {
            ulonglong2 v = suq[base + b + (b >> 2)];
            W[2 * b]     = v.x;
            W[2 * b + 1] = v.y;
        }
        const int p0 = pbase + 16 * cc;
        #pragma unroll
        for (int dp = 0; dp < 16; ++dp) {
            const ull kve = k2e[p0 + dp];
            #pragma unroll
            for (int j = 0; j < 8; ++j)
                ffma2(accE[j], kve, W[15 - dp + j]);
            const ull kvo = k2o[p0 + dp];
            #pragma unroll
            for (int j = 0; j < 8; ++j)
                ffma2(accO[j], kvo, W[16 - dp + j]);
        }
        Q0 -= 8;
    }

    // ---- combine halves + skip ----
    const float* suf = reinterpret_cast<const float*>(suq);
    const float k2047 = lo32(k2e[1023]);   // k[2047]

    if (half == 1) {
        #pragma unroll
        for (int j = 0; j < 8; ++j) {
            const int tE = 16 * i + 2 * j;
            const int tO = tE + 1;
            ybuf[tE] = lo32(accE[j]) + hi32(accE[j]);
            float o = lo32(accO[j]) + hi32(accO[j]);
            // fixup m = 2047 (odd outputs): u[tO - 1024] -> a = tO
            int a = tO;
            int Q = a >> 2;
            o += k2047 * suf[(Q + (Q >> 2)) * 4 + (a & 3)];
            ybuf[tO] = o;
        }
    }
    __syncthreads();
    if (half == 0) {
        const float dh = D[h];
        #pragma unroll
        for (int j = 0; j < 8; ++j) {
            const int tE = 16 * i + 2 * j;
            const int tO = tE + 1;
            int aE = tE + 1024, QE = aE >> 2;
            int aO = tO + 1024, QO = aO >> 2;
            float uE = suf[(QE + (QE >> 2)) * 4 + (aE & 3)];
            float uO = suf[(QO + (QO >> 2)) * 4 + (aO & 3)];
            ybuf[tE] += lo32(accE[j]) + hi32(accE[j]) + dh * uE;
            ybuf[tO] += lo32(accO[j]) + hi32(accO[j]) + dh * uO;
        }
    }
    __syncthreads();

    // coalesced store
    const float4* yb4 = reinterpret_cast<const float4*>(ybuf);
    float4* yg4 = reinterpret_cast<float4*>(y + h * Lc);
    for (int q = tid; q < Lc / 4; q += 256) yg4[q] = yb4[q];
}

// ---------------------------------------------------------------------------
extern "C" void kernel_launch(void* const* d_in, const int* in_sizes, int n_in,
                              void* d_out, int out_size)
{
    const float* u = nullptr;
    const float* C = nullptr;
    const float* D = nullptr;
    const float* K = nullptr;
    for (int i = 0; i < n_in; ++i) {
        switch (in_sizes[i]) {
            case Hc * Lc:  u = (const float*)d_in[i]; break;
            case Hc * Nc:  C = (const float*)d_in[i]; break;
            case Hc:       D = (const float*)d_in[i]; break;
            default:
                if (in_sizes[i] == Lc * Hc * Nc) K = (const float*)d_in[i];
                break;
        }
    }

    float* y = (float*)d_out;

    kl_synth_kernel<<<Lc, 256>>>(K, C);    // one block per l, contiguous 64KB
    conv_kernel<<<Hc, 256>>>(u, D, y);
}